// round 1
// baseline (speedup 1.0000x reference)
#include <cuda_runtime.h>

// DMPNN on GB300. fp32 with packed fma.rn.f32x2 GEMM cores.
// Scratch in __device__ globals (no allocation anywhere).

#define E_EDGES 1600000
#define NN      50000
#define U       128
#define KI      160          // D_NODE + D_EDGE
#define KF      256          // D_NODE + UNITS

typedef unsigned long long ull;

__device__ __align__(16) float g_h  [(size_t)E_EDGES * U];   // 819.2 MB
__device__ __align__(16) float g_h2 [(size_t)E_EDGES * U];   // 819.2 MB
__device__ __align__(16) float g_agg[(size_t)NN * U];        // 25.6 MB
__device__ int g_counts [NN];
__device__ int g_offsets[NN + 1];
__device__ int g_cursor [NN];
__device__ int g_elist  [E_EDGES];

// ---------------- packed f32x2 helpers ----------------
__device__ __forceinline__ ull fma2(ull a, ull b, ull c) {
    ull d;
    asm("fma.rn.f32x2 %0, %1, %2, %3;" : "=l"(d) : "l"(a), "l"(b), "l"(c));
    return d;
}
__device__ __forceinline__ ull pack2(float x) {
    ull d; asm("mov.b64 %0, {%1, %1};" : "=l"(d) : "f"(x)); return d;
}
__device__ __forceinline__ float2 unpack2(ull v) {
    float2 r; asm("mov.b64 {%0, %1}, %2;" : "=f"(r.x), "=f"(r.y) : "l"(v)); return r;
}

// ---------------- CSR build ----------------
__global__ void zero_counts_kernel() {
    int i = blockIdx.x * blockDim.x + threadIdx.x;
    if (i < NN) g_counts[i] = 0;
}
__global__ void hist_kernel(const int* __restrict__ dst) {
    int e = blockIdx.x * blockDim.x + threadIdx.x;
    if (e < E_EDGES) atomicAdd(&g_counts[dst[e]], 1);
}
__global__ void scan_kernel() {
    __shared__ int part[1024];
    const int T = 1024;
    const int CH = (NN + T - 1) / T;   // 49
    int t = threadIdx.x;
    int base = t * CH;
    int s = 0;
    for (int c = 0; c < CH; c++) {
        int i = base + c;
        if (i < NN) s += g_counts[i];
    }
    part[t] = s;
    __syncthreads();
    for (int off = 1; off < T; off <<= 1) {
        int v = (t >= off) ? part[t - off] : 0;
        __syncthreads();
        part[t] += v;
        __syncthreads();
    }
    int run = part[t] - s;   // exclusive prefix of this thread's chunk
    for (int c = 0; c < CH; c++) {
        int i = base + c;
        if (i < NN) {
            g_offsets[i] = run;
            g_cursor[i]  = run;
            run += g_counts[i];
        }
    }
    if (t == T - 1) g_offsets[NN] = run;
}
__global__ void fill_kernel(const int* __restrict__ dst) {
    int e = blockIdx.x * blockDim.x + threadIdx.x;
    if (e < E_EDGES) {
        int p = atomicAdd(&g_cursor[dst[e]], 1);
        g_elist[p] = e;
    }
}

// ---------------- segment sum (warp per node) ----------------
__global__ void __launch_bounds__(256) seg_sum_kernel(const float* __restrict__ h) {
    int node = (blockIdx.x * 256 + threadIdx.x) >> 5;
    int lane = threadIdx.x & 31;
    if (node >= NN) return;
    int beg = g_offsets[node], end = g_offsets[node + 1];
    float4 acc = make_float4(0.f, 0.f, 0.f, 0.f);
    for (int i = beg; i < end; ++i) {
        int e = g_elist[i];
        float4 v = *reinterpret_cast<const float4*>(h + (size_t)e * U + lane * 4);
        acc.x += v.x; acc.y += v.y; acc.z += v.z; acc.w += v.w;
    }
    *reinterpret_cast<float4*>(g_agg + (size_t)node * U + lane * 4) = acc;
}

// ---------------- shared GEMM core ----------------
// Tile: BM=64 rows x 128 cols, 128 threads. tx = tid&7, ty = tid>>3.
// Thread outputs: rows m0..m0+3 (m0=ty*4), cols n = tx*4 + j*32 + {0..3}, j<4.
// B in SMEM is [K][128] row-major; the interleaved n-mapping makes the
// ulonglong2 B loads bank-conflict-free (8 threads/phase span all 32 banks).
template<int K>
__device__ __forceinline__ void gemm_core(const float* __restrict__ As,
                                          const float* __restrict__ Bs,
                                          int m0, int tx, ull acc[4][8]) {
    #pragma unroll 2
    for (int k = 0; k < K; k += 4) {
        float4 av[4];
        #pragma unroll
        for (int i = 0; i < 4; i++)
            av[i] = *reinterpret_cast<const float4*>(As + (m0 + i) * K + k);
        #pragma unroll
        for (int kk = 0; kk < 4; kk++) {
            const float* brow = Bs + (k + kk) * U + tx * 4;
            ull b[8];
            #pragma unroll
            for (int j = 0; j < 4; j++) {
                ulonglong2 t = *reinterpret_cast<const ulonglong2*>(brow + j * 32);
                b[2 * j]     = t.x;
                b[2 * j + 1] = t.y;
            }
            #pragma unroll
            for (int i = 0; i < 4; i++) {
                ull ap = pack2(reinterpret_cast<const float*>(&av[i])[kk]);
                #pragma unroll
                for (int j = 0; j < 8; j++)
                    acc[i][j] = fma2(ap, b[j], acc[i][j]);
            }
        }
    }
}

__device__ __forceinline__ void load_weights(const float* __restrict__ W, float* Ws,
                                             int kTotal, int tid) {
    int total4 = kTotal * U / 4;
    for (int i = tid; i < total4; i += 128)
        reinterpret_cast<float4*>(Ws)[i] = reinterpret_cast<const float4*>(W)[i];
}

// ---------------- init: h = relu([x[src] || efeat] @ Wi + bi) ----------------
__global__ void __launch_bounds__(128) init_gemm_kernel(
    const float* __restrict__ xfeat, const float* __restrict__ efeat,
    const int* __restrict__ src, const float* __restrict__ Wi,
    const float* __restrict__ bi, float* __restrict__ hout)
{
    extern __shared__ float sm[];
    float* Ws = sm;              // 160*128
    float* As = sm + KI * U;     // 64*160
    int tid = threadIdx.x;
    load_weights(Wi, Ws, KI, tid);

    int e0 = blockIdx.x * 64;
    int lane = tid & 31, warp = tid >> 5;
    for (int m = warp; m < 64; m += 4) {
        int e = e0 + m;
        int s = __ldg(src + e);
        float4 v = *reinterpret_cast<const float4*>(xfeat + (size_t)s * 128 + lane * 4);
        *reinterpret_cast<float4*>(As + m * KI + lane * 4) = v;
        if (lane < 8) {
            float4 u = *reinterpret_cast<const float4*>(efeat + (size_t)e * 32 + lane * 4);
            *reinterpret_cast<float4*>(As + m * KI + 128 + lane * 4) = u;
        }
    }
    __syncthreads();

    int tx = tid & 7, ty = tid >> 3, m0 = ty * 4;
    ull acc[4][8];
    #pragma unroll
    for (int i = 0; i < 4; i++)
        #pragma unroll
        for (int j = 0; j < 8; j++) acc[i][j] = 0ull;

    gemm_core<KI>(As, Ws, m0, tx, acc);

    #pragma unroll
    for (int i = 0; i < 4; i++) {
        int e = e0 + m0 + i;
        float* hrow = hout + (size_t)e * U;
        #pragma unroll
        for (int j = 0; j < 4; j++) {
            int n = tx * 4 + j * 32;
            float2 p0 = unpack2(acc[i][2 * j]);
            float2 p1 = unpack2(acc[i][2 * j + 1]);
            float4 bv = *reinterpret_cast<const float4*>(bi + n);
            float4 o;
            o.x = fmaxf(p0.x + bv.x, 0.f);
            o.y = fmaxf(p0.y + bv.y, 0.f);
            o.z = fmaxf(p1.x + bv.z, 0.f);
            o.w = fmaxf(p1.y + bv.w, 0.f);
            *reinterpret_cast<float4*>(hrow + n) = o;
        }
    }
}

// ---------------- step: h' = relu((agg[src]-h[e^1]) @ Wu + bu + h) ----------------
__global__ void __launch_bounds__(128) step_gemm_kernel(
    const float* __restrict__ hin, float* __restrict__ hout,
    const int* __restrict__ src, const float* __restrict__ Wu,
    const float* __restrict__ bu)
{
    extern __shared__ float sm[];
    float* Ws = sm;              // 128*128
    float* As = sm + U * U;      // 64*128
    int tid = threadIdx.x;
    load_weights(Wu, Ws, U, tid);

    int e0 = blockIdx.x * 64;
    int lane = tid & 31, warp = tid >> 5;
    for (int m = warp; m < 64; m += 4) {
        int e = e0 + m;
        int s = __ldg(src + e);
        float4 a = *reinterpret_cast<const float4*>(g_agg + (size_t)s * U + lane * 4);
        float4 b = *reinterpret_cast<const float4*>(hin + (size_t)(e ^ 1) * U + lane * 4);
        float4 d = make_float4(a.x - b.x, a.y - b.y, a.z - b.z, a.w - b.w);
        *reinterpret_cast<float4*>(As + m * U + lane * 4) = d;
    }
    __syncthreads();

    int tx = tid & 7, ty = tid >> 3, m0 = ty * 4;
    ull acc[4][8];
    #pragma unroll
    for (int i = 0; i < 4; i++)
        #pragma unroll
        for (int j = 0; j < 8; j++) acc[i][j] = 0ull;

    gemm_core<U>(As, Ws, m0, tx, acc);

    #pragma unroll
    for (int i = 0; i < 4; i++) {
        int e = e0 + m0 + i;
        const float* hrow = hin + (size_t)e * U;
        float* orow = hout + (size_t)e * U;
        #pragma unroll
        for (int j = 0; j < 4; j++) {
            int n = tx * 4 + j * 32;
            float2 p0 = unpack2(acc[i][2 * j]);
            float2 p1 = unpack2(acc[i][2 * j + 1]);
            float4 bv = *reinterpret_cast<const float4*>(bu + n);
            float4 hv = *reinterpret_cast<const float4*>(hrow + n);
            float4 o;
            o.x = fmaxf(p0.x + bv.x + hv.x, 0.f);
            o.y = fmaxf(p0.y + bv.y + hv.y, 0.f);
            o.z = fmaxf(p1.x + bv.z + hv.z, 0.f);
            o.w = fmaxf(p1.y + bv.w + hv.w, 0.f);
            *reinterpret_cast<float4*>(orow + n) = o;
        }
    }
}

// ---------------- final: out = relu([x || agg] @ Wf + bf) over nodes ----------------
__global__ void __launch_bounds__(128) final_gemm_kernel(
    const float* __restrict__ xfeat, const float* __restrict__ Wf,
    const float* __restrict__ bf, float* __restrict__ out)
{
    extern __shared__ float sm[];
    float* Ws = sm;               // 256*128
    float* As = sm + KF * U;      // 64*256
    int tid = threadIdx.x;
    load_weights(Wf, Ws, KF, tid);

    int n0blk = blockIdx.x * 64;
    int lane = tid & 31, warp = tid >> 5;
    for (int m = warp; m < 64; m += 4) {
        int node = n0blk + m;
        int nc = node < NN ? node : 0;
        float4 x = *reinterpret_cast<const float4*>(xfeat + (size_t)nc * 128 + lane * 4);
        float4 g = *reinterpret_cast<const float4*>(g_agg + (size_t)nc * U + lane * 4);
        *reinterpret_cast<float4*>(As + m * KF + lane * 4) = x;
        *reinterpret_cast<float4*>(As + m * KF + 128 + lane * 4) = g;
    }
    __syncthreads();

    int tx = tid & 7, ty = tid >> 3, m0 = ty * 4;
    ull acc[4][8];
    #pragma unroll
    for (int i = 0; i < 4; i++)
        #pragma unroll
        for (int j = 0; j < 8; j++) acc[i][j] = 0ull;

    gemm_core<KF>(As, Ws, m0, tx, acc);

    #pragma unroll
    for (int i = 0; i < 4; i++) {
        int node = n0blk + m0 + i;
        if (node >= NN) continue;
        float* orow = out + (size_t)node * U;
        #pragma unroll
        for (int j = 0; j < 4; j++) {
            int n = tx * 4 + j * 32;
            float2 p0 = unpack2(acc[i][2 * j]);
            float2 p1 = unpack2(acc[i][2 * j + 1]);
            float4 bv = *reinterpret_cast<const float4*>(bf + n);
            float4 o;
            o.x = fmaxf(p0.x + bv.x, 0.f);
            o.y = fmaxf(p0.y + bv.y, 0.f);
            o.z = fmaxf(p1.x + bv.z, 0.f);
            o.w = fmaxf(p1.y + bv.w, 0.f);
            *reinterpret_cast<float4*>(orow + n) = o;
        }
    }
}

// ---------------- launch ----------------
extern "C" void kernel_launch(void* const* d_in, const int* in_sizes, int n_in,
                              void* d_out, int out_size) {
    const float* xfeat = (const float*)d_in[0];
    const float* efeat = (const float*)d_in[1];
    const int*   esrc  = (const int*)d_in[2];
    const int*   edst  = (const int*)d_in[3];
    const float* Wi    = (const float*)d_in[4];
    const float* bi    = (const float*)d_in[5];
    const float* Wu    = (const float*)d_in[6];
    const float* bu    = (const float*)d_in[7];
    const float* Wf    = (const float*)d_in[8];
    const float* bf    = (const float*)d_in[9];
    float* out = (float*)d_out;

    (void)in_sizes; (void)n_in; (void)out_size;

    const int SMEM_INIT  = (KI * U + 64 * KI) * 4;   // 122880
    const int SMEM_STEP  = (U * U + 64 * U) * 4;     //  98304
    const int SMEM_FINAL = (KF * U + 64 * KF) * 4;   // 196608
    cudaFuncSetAttribute(init_gemm_kernel,  cudaFuncAttributeMaxDynamicSharedMemorySize, SMEM_INIT);
    cudaFuncSetAttribute(step_gemm_kernel,  cudaFuncAttributeMaxDynamicSharedMemorySize, SMEM_STEP);
    cudaFuncSetAttribute(final_gemm_kernel, cudaFuncAttributeMaxDynamicSharedMemorySize, SMEM_FINAL);

    float *h0, *h1;
    cudaGetSymbolAddress((void**)&h0, g_h);
    cudaGetSymbolAddress((void**)&h1, g_h2);

    // CSR build (by edge_dst)
    zero_counts_kernel<<<(NN + 255) / 256, 256>>>();
    hist_kernel<<<E_EDGES / 256, 256>>>(edst);
    scan_kernel<<<1, 1024>>>();
    fill_kernel<<<E_EDGES / 256, 256>>>(edst);

    const int NBLK_E = E_EDGES / 64;        // 25000
    const int NBLK_N = (NN + 63) / 64;      // 782
    const int NBLK_SEG = (NN * 32 + 255) / 256;  // 6250

    init_gemm_kernel<<<NBLK_E, 128, SMEM_INIT>>>(xfeat, efeat, esrc, Wi, bi, h0);

    float* cur = h0;
    float* nxt = h1;
    for (int s = 0; s < 4; s++) {
        seg_sum_kernel<<<NBLK_SEG, 256>>>(cur);
        step_gemm_kernel<<<NBLK_E, 128, SMEM_STEP>>>(cur, nxt, esrc, Wu, bu);
        float* t = cur; cur = nxt; nxt = t;
    }
    seg_sum_kernel<<<NBLK_SEG, 256>>>(cur);
    final_gemm_kernel<<<NBLK_N, 128, SMEM_FINAL>>>(xfeat, Wf, bf, out);
}

// round 2
// speedup vs baseline: 1.1860x; 1.1860x over previous
#include <cuda_runtime.h>

// DMPNN on GB300 — fp32 with packed fma.rn.f32x2 GEMM cores.
// R2: padded A tiles (bank-conflict-free LDS), 256-thread init tile,
//     launch order arranged so ncu -s 5 captures step_gemm.

#define E_EDGES 1600000
#define NN      50000
#define U       128
#define KI      160          // D_NODE + D_EDGE
#define KF      256          // D_NODE + UNITS
#define APAD    4            // A-tile row padding (floats)

typedef unsigned long long ull;

__device__ __align__(16) float g_h  [(size_t)E_EDGES * U];   // 819.2 MB
__device__ __align__(16) float g_h2 [(size_t)E_EDGES * U];   // 819.2 MB
__device__ __align__(16) float g_agg[(size_t)NN * U];        // 25.6 MB
__device__ int g_counts [NN];          // zero at entry (BSS + re-zeroed in scan)
__device__ int g_offsets[NN + 1];
__device__ int g_cursor [NN];
__device__ int g_elist  [E_EDGES];

// ---------------- packed f32x2 helpers ----------------
__device__ __forceinline__ ull fma2(ull a, ull b, ull c) {
    ull d;
    asm("fma.rn.f32x2 %0, %1, %2, %3;" : "=l"(d) : "l"(a), "l"(b), "l"(c));
    return d;
}
__device__ __forceinline__ ull pack2(float x) {
    ull d; asm("mov.b64 %0, {%1, %1};" : "=l"(d) : "f"(x)); return d;
}
__device__ __forceinline__ float2 unpack2(ull v) {
    float2 r; asm("mov.b64 {%0, %1}, %2;" : "=f"(r.x), "=f"(r.y) : "l"(v)); return r;
}

// ---------------- CSR build ----------------
__global__ void hist_kernel(const int* __restrict__ dst) {
    int e = blockIdx.x * blockDim.x + threadIdx.x;
    if (e < E_EDGES) atomicAdd(&g_counts[dst[e]], 1);
}
__global__ void scan_kernel() {
    __shared__ int part[1024];
    const int T = 1024;
    const int CH = (NN + T - 1) / T;   // 49
    int t = threadIdx.x;
    int base = t * CH;
    int s = 0;
    for (int c = 0; c < CH; c++) {
        int i = base + c;
        if (i < NN) s += g_counts[i];
    }
    part[t] = s;
    __syncthreads();
    for (int off = 1; off < T; off <<= 1) {
        int v = (t >= off) ? part[t - off] : 0;
        __syncthreads();
        part[t] += v;
        __syncthreads();
    }
    int run = part[t] - s;   // exclusive prefix of this thread's chunk
    for (int c = 0; c < CH; c++) {
        int i = base + c;
        if (i < NN) {
            g_offsets[i] = run;
            g_cursor[i]  = run;
            run += g_counts[i];
            g_counts[i] = 0;        // re-zero for the next kernel_launch call
        }
    }
    if (t == T - 1) g_offsets[NN] = run;
}
__global__ void fill_kernel(const int* __restrict__ dst) {
    int e = blockIdx.x * blockDim.x + threadIdx.x;
    if (e < E_EDGES) {
        int p = atomicAdd(&g_cursor[dst[e]], 1);
        g_elist[p] = e;
    }
}

// ---------------- segment sum (warp per node) ----------------
__global__ void __launch_bounds__(256) seg_sum_kernel(const float* __restrict__ h) {
    int node = (blockIdx.x * 256 + threadIdx.x) >> 5;
    int lane = threadIdx.x & 31;
    if (node >= NN) return;
    int beg = g_offsets[node], end = g_offsets[node + 1];
    float4 acc = make_float4(0.f, 0.f, 0.f, 0.f);
    for (int i = beg; i < end; ++i) {
        int e = g_elist[i];
        float4 v = *reinterpret_cast<const float4*>(h + (size_t)e * U + lane * 4);
        acc.x += v.x; acc.y += v.y; acc.z += v.z; acc.w += v.w;
    }
    *reinterpret_cast<float4*>(g_agg + (size_t)node * U + lane * 4) = acc;
}

// ---------------- shared GEMM core ----------------
// Thread outputs rows m0..m0+3, cols n = tx*4 + j*32 + {0..3}, j<4.
// B in SMEM is [K][128] row-major (conflict-free: 8 distinct tx span 128B).
// A in SMEM has row stride K+APAD floats -> the 4 distinct ty rows per warp
// land in distinct 16B bank groups -> conflict-free LDS.128.
template<int K>
__device__ __forceinline__ void gemm_core(const float* __restrict__ As,
                                          const float* __restrict__ Bs,
                                          int m0, int tx, ull acc[4][8]) {
    const int LDA = K + APAD;
    #pragma unroll 2
    for (int k = 0; k < K; k += 4) {
        float4 av[4];
        #pragma unroll
        for (int i = 0; i < 4; i++)
            av[i] = *reinterpret_cast<const float4*>(As + (m0 + i) * LDA + k);
        #pragma unroll
        for (int kk = 0; kk < 4; kk++) {
            const float* brow = Bs + (k + kk) * U + tx * 4;
            ull b[8];
            #pragma unroll
            for (int j = 0; j < 4; j++) {
                ulonglong2 t = *reinterpret_cast<const ulonglong2*>(brow + j * 32);
                b[2 * j]     = t.x;
                b[2 * j + 1] = t.y;
            }
            #pragma unroll
            for (int i = 0; i < 4; i++) {
                ull ap = pack2(reinterpret_cast<const float*>(&av[i])[kk]);
                #pragma unroll
                for (int j = 0; j < 8; j++)
                    acc[i][j] = fma2(ap, b[j], acc[i][j]);
            }
        }
    }
}

template<int NT>
__device__ __forceinline__ void load_weights(const float* __restrict__ W, float* Ws,
                                             int kTotal, int tid) {
    int total4 = kTotal * U / 4;
    for (int i = tid; i < total4; i += NT)
        reinterpret_cast<float4*>(Ws)[i] = reinterpret_cast<const float4*>(W)[i];
}

// ---------------- init: h = relu([x[src] || efeat] @ Wi + bi) ----------------
// BM=128, 256 threads -> 2 warps/SMSP within one block.
__global__ void __launch_bounds__(256, 1) init_gemm_kernel(
    const float* __restrict__ xfeat, const float* __restrict__ efeat,
    const int* __restrict__ src, const float* __restrict__ Wi,
    const float* __restrict__ bi, float* __restrict__ hout)
{
    extern __shared__ float sm[];
    float* Ws = sm;                    // 160*128
    float* As = sm + KI * U;           // 128*(160+4)
    const int LDA = KI + APAD;
    int tid = threadIdx.x;
    load_weights<256>(Wi, Ws, KI, tid);

    int e0 = blockIdx.x * 128;
    int lane = tid & 31, warp = tid >> 5;
    for (int m = warp; m < 128; m += 8) {
        int e = e0 + m;
        int s = __ldg(src + e);
        float4 v = *reinterpret_cast<const float4*>(xfeat + (size_t)s * 128 + lane * 4);
        *reinterpret_cast<float4*>(As + m * LDA + lane * 4) = v;
        if (lane < 8) {
            float4 u = *reinterpret_cast<const float4*>(efeat + (size_t)e * 32 + lane * 4);
            *reinterpret_cast<float4*>(As + m * LDA + 128 + lane * 4) = u;
        }
    }
    __syncthreads();

    int tx = tid & 7, ty = tid >> 3, m0 = ty * 4;   // ty in [0,32)
    ull acc[4][8];
    #pragma unroll
    for (int i = 0; i < 4; i++)
        #pragma unroll
        for (int j = 0; j < 8; j++) acc[i][j] = 0ull;

    gemm_core<KI>(As, Ws, m0, tx, acc);

    #pragma unroll
    for (int i = 0; i < 4; i++) {
        int e = e0 + m0 + i;
        float* hrow = hout + (size_t)e * U;
        #pragma unroll
        for (int j = 0; j < 4; j++) {
            int n = tx * 4 + j * 32;
            float2 p0 = unpack2(acc[i][2 * j]);
            float2 p1 = unpack2(acc[i][2 * j + 1]);
            float4 bv = *reinterpret_cast<const float4*>(bi + n);
            float4 o;
            o.x = fmaxf(p0.x + bv.x, 0.f);
            o.y = fmaxf(p0.y + bv.y, 0.f);
            o.z = fmaxf(p1.x + bv.z, 0.f);
            o.w = fmaxf(p1.y + bv.w, 0.f);
            *reinterpret_cast<float4*>(hrow + n) = o;
        }
    }
}

// ---------------- step: h' = relu((agg[src]-h[e^1]) @ Wu + bu + h) ----------------
// BM=64, 128 threads, 2 blocks/SM.
__global__ void __launch_bounds__(128, 2) step_gemm_kernel(
    const float* __restrict__ hin, float* __restrict__ hout,
    const int* __restrict__ src, const float* __restrict__ Wu,
    const float* __restrict__ bu)
{
    extern __shared__ float sm[];
    float* Ws = sm;                    // 128*128
    float* As = sm + U * U;            // 64*(128+4)
    const int LDA = U + APAD;
    int tid = threadIdx.x;
    load_weights<128>(Wu, Ws, U, tid);

    int e0 = blockIdx.x * 64;
    int lane = tid & 31, warp = tid >> 5;
    for (int m = warp; m < 64; m += 4) {
        int e = e0 + m;
        int s = __ldg(src + e);
        float4 a = *reinterpret_cast<const float4*>(g_agg + (size_t)s * U + lane * 4);
        float4 b = *reinterpret_cast<const float4*>(hin + (size_t)(e ^ 1) * U + lane * 4);
        float4 d = make_float4(a.x - b.x, a.y - b.y, a.z - b.z, a.w - b.w);
        *reinterpret_cast<float4*>(As + m * LDA + lane * 4) = d;
    }
    __syncthreads();

    int tx = tid & 7, ty = tid >> 3, m0 = ty * 4;
    ull acc[4][8];
    #pragma unroll
    for (int i = 0; i < 4; i++)
        #pragma unroll
        for (int j = 0; j < 8; j++) acc[i][j] = 0ull;

    gemm_core<U>(As, Ws, m0, tx, acc);

    #pragma unroll
    for (int i = 0; i < 4; i++) {
        int e = e0 + m0 + i;
        const float* hrow = hin + (size_t)e * U;
        float* orow = hout + (size_t)e * U;
        #pragma unroll
        for (int j = 0; j < 4; j++) {
            int n = tx * 4 + j * 32;
            float2 p0 = unpack2(acc[i][2 * j]);
            float2 p1 = unpack2(acc[i][2 * j + 1]);
            float4 bv = *reinterpret_cast<const float4*>(bu + n);
            float4 hv = *reinterpret_cast<const float4*>(hrow + n);
            float4 o;
            o.x = fmaxf(p0.x + bv.x + hv.x, 0.f);
            o.y = fmaxf(p0.y + bv.y + hv.y, 0.f);
            o.z = fmaxf(p1.x + bv.z + hv.z, 0.f);
            o.w = fmaxf(p1.y + bv.w + hv.w, 0.f);
            *reinterpret_cast<float4*>(orow + n) = o;
        }
    }
}

// ---------------- final: out = relu([x || agg] @ Wf + bf) over nodes ----------------
__global__ void __launch_bounds__(128) final_gemm_kernel(
    const float* __restrict__ xfeat, const float* __restrict__ Wf,
    const float* __restrict__ bf, float* __restrict__ out)
{
    extern __shared__ float sm[];
    float* Ws = sm;                    // 256*128
    float* As = sm + KF * U;           // 64*(256+4)
    const int LDA = KF + APAD;
    int tid = threadIdx.x;
    load_weights<128>(Wf, Ws, KF, tid);

    int n0blk = blockIdx.x * 64;
    int lane = tid & 31, warp = tid >> 5;
    for (int m = warp; m < 64; m += 4) {
        int node = n0blk + m;
        int nc = node < NN ? node : 0;
        float4 x = *reinterpret_cast<const float4*>(xfeat + (size_t)nc * 128 + lane * 4);
        float4 g = *reinterpret_cast<const float4*>(g_agg + (size_t)nc * U + lane * 4);
        *reinterpret_cast<float4*>(As + m * LDA + lane * 4) = x;
        *reinterpret_cast<float4*>(As + m * LDA + 128 + lane * 4) = g;
    }
    __syncthreads();

    int tx = tid & 7, ty = tid >> 3, m0 = ty * 4;
    ull acc[4][8];
    #pragma unroll
    for (int i = 0; i < 4; i++)
        #pragma unroll
        for (int j = 0; j < 8; j++) acc[i][j] = 0ull;

    gemm_core<KF>(As, Ws, m0, tx, acc);

    #pragma unroll
    for (int i = 0; i < 4; i++) {
        int node = n0blk + m0 + i;
        if (node >= NN) continue;
        float* orow = out + (size_t)node * U;
        #pragma unroll
        for (int j = 0; j < 4; j++) {
            int n = tx * 4 + j * 32;
            float2 p0 = unpack2(acc[i][2 * j]);
            float2 p1 = unpack2(acc[i][2 * j + 1]);
            float4 bv = *reinterpret_cast<const float4*>(bf + n);
            float4 o;
            o.x = fmaxf(p0.x + bv.x, 0.f);
            o.y = fmaxf(p0.y + bv.y, 0.f);
            o.z = fmaxf(p1.x + bv.z, 0.f);
            o.w = fmaxf(p1.y + bv.w, 0.f);
            *reinterpret_cast<float4*>(orow + n) = o;
        }
    }
}

// ---------------- launch ----------------
extern "C" void kernel_launch(void* const* d_in, const int* in_sizes, int n_in,
                              void* d_out, int out_size) {
    const float* xfeat = (const float*)d_in[0];
    const float* efeat = (const float*)d_in[1];
    const int*   esrc  = (const int*)d_in[2];
    const int*   edst  = (const int*)d_in[3];
    const float* Wi    = (const float*)d_in[4];
    const float* bi    = (const float*)d_in[5];
    const float* Wu    = (const float*)d_in[6];
    const float* bu    = (const float*)d_in[7];
    const float* Wf    = (const float*)d_in[8];
    const float* bf    = (const float*)d_in[9];
    float* out = (float*)d_out;

    (void)in_sizes; (void)n_in; (void)out_size;

    const int SMEM_INIT  = (KI * U + 128 * (KI + APAD)) * 4;  // 165888
    const int SMEM_STEP  = (U * U + 64 * (U + APAD)) * 4;     //  99328
    const int SMEM_FINAL = (KF * U + 64 * (KF + APAD)) * 4;   // 197632
    cudaFuncSetAttribute(init_gemm_kernel,  cudaFuncAttributeMaxDynamicSharedMemorySize, SMEM_INIT);
    cudaFuncSetAttribute(step_gemm_kernel,  cudaFuncAttributeMaxDynamicSharedMemorySize, SMEM_STEP);
    cudaFuncSetAttribute(final_gemm_kernel, cudaFuncAttributeMaxDynamicSharedMemorySize, SMEM_FINAL);

    float *h0, *h1;
    cudaGetSymbolAddress((void**)&h0, g_h);
    cudaGetSymbolAddress((void**)&h1, g_h2);

    const int NBLK_E128 = E_EDGES / 128;            // 12500 (init)
    const int NBLK_E64  = E_EDGES / 64;             // 25000 (step)
    const int NBLK_N    = (NN + 63) / 64;           // 782
    const int NBLK_SEG  = (NN * 32 + 255) / 256;    // 6250

    // Launch order chosen so ncu -s 5 lands on a step_gemm_kernel:
    // 0:init 1:hist 2:scan 3:fill 4:seg 5:step ...
    init_gemm_kernel<<<NBLK_E128, 256, SMEM_INIT>>>(xfeat, efeat, esrc, Wi, bi, h0);

    hist_kernel<<<E_EDGES / 256, 256>>>(edst);      // counts are zero at entry
    scan_kernel<<<1, 1024>>>();                     // also re-zeroes counts
    fill_kernel<<<E_EDGES / 256, 256>>>(edst);

    float* cur = h0;
    float* nxt = h1;
    for (int s = 0; s < 4; s++) {
        seg_sum_kernel<<<NBLK_SEG, 256>>>(cur);
        step_gemm_kernel<<<NBLK_E64, 128, SMEM_STEP>>>(cur, nxt, esrc, Wu, bu);
        float* t = cur; cur = nxt; nxt = t;
    }
    seg_sum_kernel<<<NBLK_SEG, 256>>>(cur);
    final_gemm_kernel<<<NBLK_N, 128, SMEM_FINAL>>>(xfeat, Wf, bf, out);
}